// round 15
// baseline (speedup 1.0000x reference)
#include <cuda_runtime.h>
#include <cuda_bf16.h>
#include <math.h>

#define NBATCH 4
#define SEQ    2048
#define EMB    1024
#define NH     16
#define HD     64
#define FFND   4096
#define NROWS  (NBATCH*SEQ)          // 8192
#define NHEADROWS (NROWS*NH)         // 131072

// ---------------- scratch (static device allocations; no cudaMalloc) -------
__device__ float g_xn  [(size_t)NROWS*EMB];
__device__ float g_q   [(size_t)NROWS*EMB];
__device__ float g_k   [(size_t)NROWS*EMB];
__device__ float g_v   [(size_t)NROWS*EMB];
__device__ float g_ctx [(size_t)NROWS*EMB];
__device__ float g_attn[(size_t)NROWS*EMB];
__device__ float g_an  [(size_t)NROWS*EMB];
__device__ float g_ff1 [(size_t)NROWS*FFND];

// ---------------------------------------------------------------------------
// LayerNorm: one block (256 thr) per row of 1024
// ---------------------------------------------------------------------------
__global__ void __launch_bounds__(256) ln_kernel(
    const float* __restrict__ x, const float* __restrict__ g,
    const float* __restrict__ b, float* __restrict__ y)
{
    int row = blockIdx.x;
    const float4* xr = reinterpret_cast<const float4*>(x + (size_t)row * EMB);
    float4 v = xr[threadIdx.x];
    float s  = v.x + v.y + v.z + v.w;
    float s2 = v.x*v.x + v.y*v.y + v.z*v.z + v.w*v.w;

    __shared__ float rs[8], rs2[8], stat[2];
    int lane = threadIdx.x & 31, w = threadIdx.x >> 5;
#pragma unroll
    for (int o = 16; o; o >>= 1) {
        s  += __shfl_xor_sync(0xffffffffu, s,  o);
        s2 += __shfl_xor_sync(0xffffffffu, s2, o);
    }
    if (lane == 0) { rs[w] = s; rs2[w] = s2; }
    __syncthreads();
    if (threadIdx.x == 0) {
        float ts = 0.f, ts2 = 0.f;
#pragma unroll
        for (int i = 0; i < 8; i++) { ts += rs[i]; ts2 += rs2[i]; }
        float mu  = ts * (1.0f / EMB);
        float var = ts2 * (1.0f / EMB) - mu * mu;
        stat[0] = mu;
        stat[1] = rsqrtf(var + 1e-5f);
    }
    __syncthreads();
    float mu = stat[0], rstd = stat[1];
    float4 gv = reinterpret_cast<const float4*>(g)[threadIdx.x];
    float4 bv = reinterpret_cast<const float4*>(b)[threadIdx.x];
    float4 o4;
    o4.x = (v.x - mu) * rstd * gv.x + bv.x;
    o4.y = (v.y - mu) * rstd * gv.y + bv.y;
    o4.z = (v.z - mu) * rstd * gv.z + bv.z;
    o4.w = (v.w - mu) * rstd * gv.w + bv.w;
    reinterpret_cast<float4*>(y + (size_t)row * EMB)[threadIdx.x] = o4;
}

// ---------------------------------------------------------------------------
// Fused QKV per-head projection. W's are 64x64 [in,out]. Output layout
// q/k/v: [(n*NH+h)*SEQ + s]*64 + e  (head-major, for attention locality)
// dyn smem: 3*4096 + 256 floats = 50176 B
// ---------------------------------------------------------------------------
#define QKV_SMEM (size_t)((3*4096 + 256) * sizeof(float))
__global__ void __launch_bounds__(256) qkv_kernel(
    const float* __restrict__ xn,
    const float* __restrict__ Wq, const float* __restrict__ Wk,
    const float* __restrict__ Wv,
    float* __restrict__ q, float* __restrict__ k, float* __restrict__ v)
{
    extern __shared__ float sm[];
    float* sWq = sm;
    float* sWk = sm + 4096;
    float* sWv = sm + 8192;
    float* sh  = sm + 12288;     // 4 rows x 64
    int tid = threadIdx.x;
    for (int i = tid; i < 4096; i += 256) {
        sWq[i] = Wq[i]; sWk[i] = Wk[i]; sWv[i] = Wv[i];
    }
    int r = tid >> 6;            // 0..3
    int e = tid & 63;

    for (int base = blockIdx.x * 4; base < NHEADROWS; base += gridDim.x * 4) {
        __syncthreads();                           // W ready / sh free
        sh[tid] = xn[(size_t)base * 64 + tid];     // 4 contiguous head-rows
        __syncthreads();

        float aq = 0.f, ak = 0.f, av = 0.f;
#pragma unroll
        for (int d = 0; d < 64; d++) {
            float hv = sh[r * 64 + d];
            aq = fmaf(hv, sWq[d * 64 + e], aq);
            ak = fmaf(hv, sWk[d * 64 + e], ak);
            av = fmaf(hv, sWv[d * 64 + e], av);
        }
        int rg  = base + r;                         // (n*SEQ+s)*NH + h
        int n   = rg >> 15;                         // / (SEQ*NH)
        int rem = rg & 32767;
        int s   = rem >> 4;
        int h   = rem & 15;
        size_t oi = (((size_t)(n * NH + h)) * SEQ + s) * 64 + e;
        q[oi] = aq; k[oi] = ak; v[oi] = av;
    }
}

// ---------------------------------------------------------------------------
// Flash attention fp32, non-causal, scale = 1/sqrt(EMB) = 1/32.
// grid (32 qtiles, 64 nh), block 256 = 16x16 threads, each 4x4 microtile.
// smem (dyn): Qt/Kt/Vs/Ps each [64][68] + stats  -> 70,400 B
// ---------------------------------------------------------------------------
#define APAD 68
#define ATT_SMEM (size_t)((4*64*APAD + 3*64) * sizeof(float))
__global__ void __launch_bounds__(256) attn_kernel(
    const float* __restrict__ Q, const float* __restrict__ K,
    const float* __restrict__ V, float* __restrict__ ctx)
{
    extern __shared__ float sm[];
    float* Qt  = sm;                 // [d][row]
    float* Kt  = Qt + 64 * APAD;     // [d][col]
    float* Vs  = Kt + 64 * APAD;     // [k][j]
    float* Ps  = Vs + 64 * APAD;     // [row][k]
    float* m_s = Ps + 64 * APAD;
    float* l_s = m_s + 64;
    float* c_s = l_s + 64;

    const int tid = threadIdx.x;
    const int ty  = tid >> 4;        // 0..15
    const int tx  = tid & 15;        // 0..15
    const int nh  = blockIdx.y;
    const int q0  = blockIdx.x * 64;
    const size_t base = (size_t)nh * SEQ * 64;
    const float scale = 0.03125f;    // 1/32

    // load Q tile transposed
    {
        int d  = tid & 63;
        int r0 = (tid >> 6) * 16;
#pragma unroll
        for (int i = 0; i < 16; i++) {
            int r = r0 + i;
            Qt[d * APAD + r] = Q[base + (size_t)(q0 + r) * 64 + d];
        }
    }
    if (tid < 64) { m_s[tid] = -1e30f; l_s[tid] = 0.f; }

    float o[4][4];
#pragma unroll
    for (int i = 0; i < 4; i++)
#pragma unroll
        for (int j = 0; j < 4; j++) o[i][j] = 0.f;

    __syncthreads();

    for (int t = 0; t < SEQ / 64; t++) {
        int k0 = t * 64;
        // load K transposed + V direct
        {
            int d  = tid & 63;
            int c0 = (tid >> 6) * 16;
#pragma unroll
            for (int i = 0; i < 16; i++) {
                int c = c0 + i;
                Kt[d * APAD + c] = K[base + (size_t)(k0 + c) * 64 + d];
            }
#pragma unroll
            for (int i = 0; i < 16; i++) {
                int kk = c0 + i;
                Vs[kk * APAD + d] = V[base + (size_t)(k0 + kk) * 64 + d];
            }
        }
        __syncthreads();

        // S = Q K^T * scale
        float acc[4][4];
#pragma unroll
        for (int i = 0; i < 4; i++)
#pragma unroll
            for (int j = 0; j < 4; j++) acc[i][j] = 0.f;
#pragma unroll
        for (int d = 0; d < 64; d++) {
            float4 qv = *reinterpret_cast<const float4*>(&Qt[d * APAD + ty * 4]);
            float4 kv = *reinterpret_cast<const float4*>(&Kt[d * APAD + tx * 4]);
            float qa[4] = {qv.x, qv.y, qv.z, qv.w};
            float ka[4] = {kv.x, kv.y, kv.z, kv.w};
#pragma unroll
            for (int i = 0; i < 4; i++)
#pragma unroll
                for (int j = 0; j < 4; j++)
                    acc[i][j] = fmaf(qa[i], ka[j], acc[i][j]);
        }
#pragma unroll
        for (int i = 0; i < 4; i++)
#pragma unroll
            for (int j = 0; j < 4; j++)
                Ps[(ty * 4 + i) * APAD + tx * 4 + j] = acc[i][j] * scale;
        __syncthreads();

        // online softmax: warp w handles rows w*8 .. w*8+7
        {
            int w = tid >> 5, lane = tid & 31;
#pragma unroll
            for (int rr = 0; rr < 8; rr++) {
                int row = w * 8 + rr;
                float s0 = Ps[row * APAD + lane];
                float s1 = Ps[row * APAD + lane + 32];
                float mx = fmaxf(s0, s1);
#pragma unroll
                for (int off = 16; off; off >>= 1)
                    mx = fmaxf(mx, __shfl_xor_sync(0xffffffffu, mx, off));
                float m_old = m_s[row];
                float m_new = fmaxf(m_old, mx);
                float p0 = __expf(s0 - m_new);
                float p1 = __expf(s1 - m_new);
                float ps = p0 + p1;
#pragma unroll
                for (int off = 16; off; off >>= 1)
                    ps += __shfl_xor_sync(0xffffffffu, ps, off);
                float corr = __expf(m_old - m_new);
                if (lane == 0) {
                    l_s[row] = l_s[row] * corr + ps;
                    m_s[row] = m_new;
                    c_s[row] = corr;
                }
                Ps[row * APAD + lane]      = p0;
                Ps[row * APAD + lane + 32] = p1;
            }
        }
        __syncthreads();

        // rescale O and accumulate P@V
        float cr[4];
#pragma unroll
        for (int i = 0; i < 4; i++) cr[i] = c_s[ty * 4 + i];
#pragma unroll
        for (int i = 0; i < 4; i++)
#pragma unroll
            for (int j = 0; j < 4; j++) o[i][j] *= cr[i];

#pragma unroll
        for (int kk = 0; kk < 64; kk++) {
            float4 vv = *reinterpret_cast<const float4*>(&Vs[kk * APAD + tx * 4]);
            float va[4] = {vv.x, vv.y, vv.z, vv.w};
            float pa[4];
#pragma unroll
            for (int i = 0; i < 4; i++) pa[i] = Ps[(ty * 4 + i) * APAD + kk];
#pragma unroll
            for (int i = 0; i < 4; i++)
#pragma unroll
                for (int j = 0; j < 4; j++)
                    o[i][j] = fmaf(pa[i], va[j], o[i][j]);
        }
        __syncthreads();
    }

    // finalize: divide by l, write ctx in [n, s, h*64+e] layout
    int n = nh >> 4, h = nh & 15;
#pragma unroll
    for (int i = 0; i < 4; i++) {
        float inv_l = 1.0f / l_s[ty * 4 + i];
        int sg = q0 + ty * 4 + i;
        size_t ro = ((size_t)(n * SEQ + sg)) * EMB + h * 64 + tx * 4;
#pragma unroll
        for (int j = 0; j < 4; j++)
            ctx[ro + j] = o[i][j] * inv_l;
    }
}

// ---------------------------------------------------------------------------
// SGEMM 128x128x16, 256 threads, 8x8 microtile (split 4+4 rows/cols).
// C = epilogue(A[MxK] @ B[KxN] + bias[N] [, add])
// EPI 0/2: + add (residual).  EPI 1: exact GELU.
// ---------------------------------------------------------------------------
template <int EPI>
__global__ void __launch_bounds__(256) sgemm_kernel(
    const float* __restrict__ A, const float* __restrict__ B,
    const float* __restrict__ bias, const float* __restrict__ add,
    float* __restrict__ C, int M, int N, int K)
{
    __shared__ float As[16][128];
    __shared__ float Bs[16][128];

    const int tid = threadIdx.x;
    const int ty  = tid >> 4;          // 0..15
    const int tx  = tid & 15;          // 0..15
    const int m0  = blockIdx.y * 128;
    const int n0  = blockIdx.x * 128;

    float acc[8][8];
#pragma unroll
    for (int i = 0; i < 8; i++)
#pragma unroll
        for (int j = 0; j < 8; j++) acc[i][j] = 0.f;

    const int arow = tid >> 2;          // 0..63  (+64 on 2nd pass)
    const int kq   = (tid & 3) * 4;     // 0,4,8,12
    const int brow = tid >> 5;          // 0..7   (+8 on 2nd pass)
    const int bcol = (tid & 31) * 4;

    for (int kt = 0; kt < K; kt += 16) {
        // A tile -> transposed smem
#pragma unroll
        for (int p = 0; p < 2; p++) {
            int ar = arow + p * 64;
            float4 a = *reinterpret_cast<const float4*>(
                &A[(size_t)(m0 + ar) * K + kt + kq]);
            As[kq + 0][ar] = a.x;
            As[kq + 1][ar] = a.y;
            As[kq + 2][ar] = a.z;
            As[kq + 3][ar] = a.w;
        }
        // B tile direct
#pragma unroll
        for (int p = 0; p < 2; p++) {
            int br = brow + p * 8;
            *reinterpret_cast<float4*>(&Bs[br][bcol]) =
                *reinterpret_cast<const float4*>(&B[(size_t)(kt + br) * N + n0 + bcol]);
        }
        __syncthreads();

#pragma unroll
        for (int k = 0; k < 16; k++) {
            float4 a0 = *reinterpret_cast<const float4*>(&As[k][ty * 4]);
            float4 a1 = *reinterpret_cast<const float4*>(&As[k][64 + ty * 4]);
            float4 b0 = *reinterpret_cast<const float4*>(&Bs[k][tx * 4]);
            float4 b1 = *reinterpret_cast<const float4*>(&Bs[k][64 + tx * 4]);
            float ra[8] = {a0.x, a0.y, a0.z, a0.w, a1.x, a1.y, a1.z, a1.w};
            float rb[8] = {b0.x, b0.y, b0.z, b0.w, b1.x, b1.y, b1.z, b1.w};
#pragma unroll
            for (int i = 0; i < 8; i++)
#pragma unroll
                for (int j = 0; j < 8; j++)
                    acc[i][j] = fmaf(ra[i], rb[j], acc[i][j]);
        }
        __syncthreads();
    }

    // epilogue (vectorized float4 stores)
#pragma unroll
    for (int ih = 0; ih < 2; ih++) {
#pragma unroll
        for (int i = 0; i < 4; i++) {
            int row = m0 + ih * 64 + ty * 4 + i;
#pragma unroll
            for (int jh = 0; jh < 2; jh++) {
                int col = n0 + jh * 64 + tx * 4;
                float4 r;
                r.x = acc[ih * 4 + i][jh * 4 + 0];
                r.y = acc[ih * 4 + i][jh * 4 + 1];
                r.z = acc[ih * 4 + i][jh * 4 + 2];
                r.w = acc[ih * 4 + i][jh * 4 + 3];
                float4 bb = *reinterpret_cast<const float4*>(&bias[col]);
                r.x += bb.x; r.y += bb.y; r.z += bb.z; r.w += bb.w;
                if (EPI == 1) {
                    r.x = r.x * normcdff(r.x);
                    r.y = r.y * normcdff(r.y);
                    r.z = r.z * normcdff(r.z);
                    r.w = r.w * normcdff(r.w);
                } else {
                    float4 ad = *reinterpret_cast<const float4*>(
                        &add[(size_t)row * N + col]);
                    r.x += ad.x; r.y += ad.y; r.z += ad.z; r.w += ad.w;
                }
                *reinterpret_cast<float4*>(&C[(size_t)row * N + col]) = r;
            }
        }
    }
}

// ---------------------------------------------------------------------------
extern "C" void kernel_launch(void* const* d_in, const int* in_sizes, int n_in,
                              void* d_out, int out_size)
{
    const float* x     = (const float*)d_in[0];
    const float* Wq    = (const float*)d_in[1];
    const float* Wk    = (const float*)d_in[2];
    const float* Wv    = (const float*)d_in[3];
    const float* Wo    = (const float*)d_in[4];
    const float* bo    = (const float*)d_in[5];
    const float* ln1g  = (const float*)d_in[6];
    const float* ln1b  = (const float*)d_in[7];
    const float* ln2g  = (const float*)d_in[8];
    const float* ln2b  = (const float*)d_in[9];
    const float* W1    = (const float*)d_in[10];
    const float* b1    = (const float*)d_in[11];
    const float* W2    = (const float*)d_in[12];
    const float* b2    = (const float*)d_in[13];
    float* out = (float*)d_out;

    void *p_xn, *p_q, *p_k, *p_v, *p_ctx, *p_attn, *p_an, *p_ff1;
    cudaGetSymbolAddress(&p_xn,   g_xn);
    cudaGetSymbolAddress(&p_q,    g_q);
    cudaGetSymbolAddress(&p_k,    g_k);
    cudaGetSymbolAddress(&p_v,    g_v);
    cudaGetSymbolAddress(&p_ctx,  g_ctx);
    cudaGetSymbolAddress(&p_attn, g_attn);
    cudaGetSymbolAddress(&p_an,   g_an);
    cudaGetSymbolAddress(&p_ff1,  g_ff1);
    float* xn   = (float*)p_xn;
    float* q    = (float*)p_q;
    float* k    = (float*)p_k;
    float* v    = (float*)p_v;
    float* ctx  = (float*)p_ctx;
    float* attn = (float*)p_attn;
    float* an   = (float*)p_an;
    float* ff1  = (float*)p_ff1;

    cudaFuncSetAttribute(qkv_kernel,  cudaFuncAttributeMaxDynamicSharedMemorySize, (int)QKV_SMEM);
    cudaFuncSetAttribute(attn_kernel, cudaFuncAttributeMaxDynamicSharedMemorySize, (int)ATT_SMEM);

    // 1. pre-LN
    ln_kernel<<<NROWS, 256>>>(x, ln1g, ln1b, xn);
    // 2. per-head QKV projections (head-major output)
    qkv_kernel<<<2048, 256, QKV_SMEM>>>(xn, Wq, Wk, Wv, q, k, v);
    // 3. flash attention -> ctx [n,s,E]
    attn_kernel<<<dim3(SEQ / 64, NBATCH * NH), 256, ATT_SMEM>>>(q, k, v, ctx);
    // 4. output projection + residual 1
    sgemm_kernel<0><<<dim3(EMB / 128, NROWS / 128), 256>>>(ctx, Wo, bo, x, attn,
                                                           NROWS, EMB, EMB);
    // 5. LN2
    ln_kernel<<<NROWS, 256>>>(attn, ln2g, ln2b, an);
    // 6. FFN up + exact GELU
    sgemm_kernel<1><<<dim3(FFND / 128, NROWS / 128), 256>>>(an, W1, b1, nullptr, ff1,
                                                            NROWS, FFND, EMB);
    // 7. FFN down + bias + residual 2 -> out
    sgemm_kernel<2><<<dim3(EMB / 128, NROWS / 128), 256>>>(ff1, W2, b2, attn, out,
                                                           NROWS, EMB, FFND);
}

// round 16
// speedup vs baseline: 1.0923x; 1.0923x over previous
#include <cuda_runtime.h>
#include <cuda_bf16.h>
#include <math.h>

#define NBATCH 4
#define SEQ    2048
#define EMB    1024
#define NH     16
#define HD     64
#define FFND   4096
#define NROWS  (NBATCH*SEQ)          // 8192
#define NHEADROWS (NROWS*NH)         // 131072

// ---------------- scratch (static device allocations; no cudaMalloc) -------
__device__ float g_xn  [(size_t)NROWS*EMB];
__device__ float g_q   [(size_t)NROWS*EMB];
__device__ float g_k   [(size_t)NROWS*EMB];
__device__ float g_v   [(size_t)NROWS*EMB];
__device__ float g_ctx [(size_t)NROWS*EMB];
__device__ float g_attn[(size_t)NROWS*EMB];
__device__ float g_an  [(size_t)NROWS*EMB];
__device__ float g_ff1 [(size_t)NROWS*FFND];

// ---------------------------------------------------------------------------
// LayerNorm: one block (256 thr) per row of 1024
// ---------------------------------------------------------------------------
__global__ void __launch_bounds__(256) ln_kernel(
    const float* __restrict__ x, const float* __restrict__ g,
    const float* __restrict__ b, float* __restrict__ y)
{
    int row = blockIdx.x;
    const float4* xr = reinterpret_cast<const float4*>(x + (size_t)row * EMB);
    float4 v = xr[threadIdx.x];
    float s  = v.x + v.y + v.z + v.w;
    float s2 = v.x*v.x + v.y*v.y + v.z*v.z + v.w*v.w;

    __shared__ float rs[8], rs2[8], stat[2];
    int lane = threadIdx.x & 31, w = threadIdx.x >> 5;
#pragma unroll
    for (int o = 16; o; o >>= 1) {
        s  += __shfl_xor_sync(0xffffffffu, s,  o);
        s2 += __shfl_xor_sync(0xffffffffu, s2, o);
    }
    if (lane == 0) { rs[w] = s; rs2[w] = s2; }
    __syncthreads();
    if (threadIdx.x == 0) {
        float ts = 0.f, ts2 = 0.f;
#pragma unroll
        for (int i = 0; i < 8; i++) { ts += rs[i]; ts2 += rs2[i]; }
        float mu  = ts * (1.0f / EMB);
        float var = ts2 * (1.0f / EMB) - mu * mu;
        stat[0] = mu;
        stat[1] = rsqrtf(var + 1e-5f);
    }
    __syncthreads();
    float mu = stat[0], rstd = stat[1];
    float4 gv = reinterpret_cast<const float4*>(g)[threadIdx.x];
    float4 bv = reinterpret_cast<const float4*>(b)[threadIdx.x];
    float4 o4;
    o4.x = (v.x - mu) * rstd * gv.x + bv.x;
    o4.y = (v.y - mu) * rstd * gv.y + bv.y;
    o4.z = (v.z - mu) * rstd * gv.z + bv.z;
    o4.w = (v.w - mu) * rstd * gv.w + bv.w;
    reinterpret_cast<float4*>(y + (size_t)row * EMB)[threadIdx.x] = o4;
}

// ---------------------------------------------------------------------------
// Fused QKV per-head projection. W's are 64x64 [in,out]. Output layout
// q/k/v: [(n*NH+h)*SEQ + s]*64 + e  (head-major, for attention locality)
// ---------------------------------------------------------------------------
#define QKV_SMEM (size_t)((3*4096 + 256) * sizeof(float))
__global__ void __launch_bounds__(256) qkv_kernel(
    const float* __restrict__ xn,
    const float* __restrict__ Wq, const float* __restrict__ Wk,
    const float* __restrict__ Wv,
    float* __restrict__ q, float* __restrict__ k, float* __restrict__ v)
{
    extern __shared__ float sm[];
    float* sWq = sm;
    float* sWk = sm + 4096;
    float* sWv = sm + 8192;
    float* sh  = sm + 12288;     // 4 rows x 64
    int tid = threadIdx.x;
    for (int i = tid; i < 4096; i += 256) {
        sWq[i] = Wq[i]; sWk[i] = Wk[i]; sWv[i] = Wv[i];
    }
    int r = tid >> 6;            // 0..3
    int e = tid & 63;

    for (int base = blockIdx.x * 4; base < NHEADROWS; base += gridDim.x * 4) {
        __syncthreads();                           // W ready / sh free
        sh[tid] = xn[(size_t)base * 64 + tid];     // 4 contiguous head-rows
        __syncthreads();

        float aq = 0.f, ak = 0.f, av = 0.f;
#pragma unroll
        for (int d = 0; d < 64; d++) {
            float hv = sh[r * 64 + d];
            aq = fmaf(hv, sWq[d * 64 + e], aq);
            ak = fmaf(hv, sWk[d * 64 + e], ak);
            av = fmaf(hv, sWv[d * 64 + e], av);
        }
        int rg  = base + r;                         // (n*SEQ+s)*NH + h
        int n   = rg >> 15;
        int rem = rg & 32767;
        int s   = rem >> 4;
        int h   = rem & 15;
        size_t oi = (((size_t)(n * NH + h)) * SEQ + s) * 64 + e;
        q[oi] = aq; k[oi] = ak; v[oi] = av;
    }
}

// ---------------------------------------------------------------------------
// Flash attention fp32, non-causal, scale = 1/sqrt(EMB) = 1/32.
// grid (32 qtiles, 64 nh), block 256 = 16x16 threads, each 4x4 microtile.
// ---------------------------------------------------------------------------
#define APAD 68
#define ATT_SMEM (size_t)((4*64*APAD + 3*64) * sizeof(float))
__global__ void __launch_bounds__(256) attn_kernel(
    const float* __restrict__ Q, const float* __restrict__ K,
    const float* __restrict__ V, float* __restrict__ ctx)
{
    extern __shared__ float sm[];
    float* Qt  = sm;                 // [d][row]
    float* Kt  = Qt + 64 * APAD;     // [d][col]
    float* Vs  = Kt + 64 * APAD;     // [k][j]
    float* Ps  = Vs + 64 * APAD;     // [row][k]
    float* m_s = Ps + 64 * APAD;
    float* l_s = m_s + 64;
    float* c_s = l_s + 64;

    const int tid = threadIdx.x;
    const int ty  = tid >> 4;        // 0..15
    const int tx  = tid & 15;        // 0..15
    const int nh  = blockIdx.y;
    const int q0  = blockIdx.x * 64;
    const size_t base = (size_t)nh * SEQ * 64;
    const float scale = 0.03125f;    // 1/32

    // load Q tile transposed
    {
        int d  = tid & 63;
        int r0 = (tid >> 6) * 16;
#pragma unroll
        for (int i = 0; i < 16; i++) {
            int r = r0 + i;
            Qt[d * APAD + r] = Q[base + (size_t)(q0 + r) * 64 + d];
        }
    }
    if (tid < 64) { m_s[tid] = -1e30f; l_s[tid] = 0.f; }

    float o[4][4];
#pragma unroll
    for (int i = 0; i < 4; i++)
#pragma unroll
        for (int j = 0; j < 4; j++) o[i][j] = 0.f;

    __syncthreads();

    for (int t = 0; t < SEQ / 64; t++) {
        int k0 = t * 64;
        // load K transposed + V direct
        {
            int d  = tid & 63;
            int c0 = (tid >> 6) * 16;
#pragma unroll
            for (int i = 0; i < 16; i++) {
                int c = c0 + i;
                Kt[d * APAD + c] = K[base + (size_t)(k0 + c) * 64 + d];
            }
#pragma unroll
            for (int i = 0; i < 16; i++) {
                int kk = c0 + i;
                Vs[kk * APAD + d] = V[base + (size_t)(k0 + kk) * 64 + d];
            }
        }
        __syncthreads();

        // S = Q K^T * scale
        float acc[4][4];
#pragma unroll
        for (int i = 0; i < 4; i++)
#pragma unroll
            for (int j = 0; j < 4; j++) acc[i][j] = 0.f;
#pragma unroll
        for (int d = 0; d < 64; d++) {
            float4 qv = *reinterpret_cast<const float4*>(&Qt[d * APAD + ty * 4]);
            float4 kv = *reinterpret_cast<const float4*>(&Kt[d * APAD + tx * 4]);
            float qa[4] = {qv.x, qv.y, qv.z, qv.w};
            float ka[4] = {kv.x, kv.y, kv.z, kv.w};
#pragma unroll
            for (int i = 0; i < 4; i++)
#pragma unroll
                for (int j = 0; j < 4; j++)
                    acc[i][j] = fmaf(qa[i], ka[j], acc[i][j]);
        }
#pragma unroll
        for (int i = 0; i < 4; i++)
#pragma unroll
            for (int j = 0; j < 4; j++)
                Ps[(ty * 4 + i) * APAD + tx * 4 + j] = acc[i][j] * scale;
        __syncthreads();

        // online softmax: warp w handles rows w*8 .. w*8+7
        {
            int w = tid >> 5, lane = tid & 31;
#pragma unroll
            for (int rr = 0; rr < 8; rr++) {
                int row = w * 8 + rr;
                float s0 = Ps[row * APAD + lane];
                float s1 = Ps[row * APAD + lane + 32];
                float mx = fmaxf(s0, s1);
#pragma unroll
                for (int off = 16; off; off >>= 1)
                    mx = fmaxf(mx, __shfl_xor_sync(0xffffffffu, mx, off));
                float m_old = m_s[row];
                float m_new = fmaxf(m_old, mx);
                float p0 = __expf(s0 - m_new);
                float p1 = __expf(s1 - m_new);
                float ps = p0 + p1;
#pragma unroll
                for (int off = 16; off; off >>= 1)
                    ps += __shfl_xor_sync(0xffffffffu, ps, off);
                float corr = __expf(m_old - m_new);
                if (lane == 0) {
                    l_s[row] = l_s[row] * corr + ps;
                    m_s[row] = m_new;
                    c_s[row] = corr;
                }
                Ps[row * APAD + lane]      = p0;
                Ps[row * APAD + lane + 32] = p1;
            }
        }
        __syncthreads();

        // rescale O and accumulate P@V (kk chunked by 4, float4 P loads)
        float cr[4];
#pragma unroll
        for (int i = 0; i < 4; i++) cr[i] = c_s[ty * 4 + i];
#pragma unroll
        for (int i = 0; i < 4; i++)
#pragma unroll
            for (int j = 0; j < 4; j++) o[i][j] *= cr[i];

#pragma unroll
        for (int kk0 = 0; kk0 < 64; kk0 += 4) {
            float pav[4][4];
#pragma unroll
            for (int i = 0; i < 4; i++) {
                float4 p4 = *reinterpret_cast<const float4*>(
                    &Ps[(ty * 4 + i) * APAD + kk0]);
                pav[i][0] = p4.x; pav[i][1] = p4.y;
                pav[i][2] = p4.z; pav[i][3] = p4.w;
            }
#pragma unroll
            for (int kkk = 0; kkk < 4; kkk++) {
                float4 vv = *reinterpret_cast<const float4*>(
                    &Vs[(kk0 + kkk) * APAD + tx * 4]);
                float va[4] = {vv.x, vv.y, vv.z, vv.w};
#pragma unroll
                for (int i = 0; i < 4; i++)
#pragma unroll
                    for (int j = 0; j < 4; j++)
                        o[i][j] = fmaf(pav[i][kkk], va[j], o[i][j]);
            }
        }
        __syncthreads();
    }

    // finalize: divide by l, write ctx in [n, s, h*64+e] layout
    int n = nh >> 4, h = nh & 15;
#pragma unroll
    for (int i = 0; i < 4; i++) {
        float inv_l = 1.0f / l_s[ty * 4 + i];
        int sg = q0 + ty * 4 + i;
        size_t ro = ((size_t)(n * SEQ + sg)) * EMB + h * 64 + tx * 4;
#pragma unroll
        for (int j = 0; j < 4; j++)
            ctx[ro + j] = o[i][j] * inv_l;
    }
}

// ---------------------------------------------------------------------------
// SGEMM 128x128x16, 256 threads, 8x8 microtile, DOUBLE-BUFFERED smem with
// register prefetch of the next global tile (hides DRAM latency), one
// __syncthreads per k-tile. __launch_bounds__(256,2) keeps 2 CTAs/SM.
// C = epilogue(A[MxK] @ B[KxN] + bias[N] [, add])
// EPI 0/2: + add (residual).  EPI 1: exact GELU.
// ---------------------------------------------------------------------------
template <int EPI>
__global__ void __launch_bounds__(256, 2) sgemm_kernel(
    const float* __restrict__ A, const float* __restrict__ B,
    const float* __restrict__ bias, const float* __restrict__ add,
    float* __restrict__ C, int M, int N, int K)
{
    __shared__ float As[2][16][128];
    __shared__ float Bs[2][16][128];

    const int tid = threadIdx.x;
    const int ty  = tid >> 4;          // 0..15
    const int tx  = tid & 15;          // 0..15
    const int m0  = blockIdx.y * 128;
    const int n0  = blockIdx.x * 128;

    const int arow = tid >> 2;          // 0..63  (+64 on 2nd fragment)
    const int kq   = (tid & 3) * 4;     // 0,4,8,12
    const int brow = tid >> 5;          // 0..7   (+8 on 2nd fragment)
    const int bcol = (tid & 31) * 4;

    const float* Aptr = A + (size_t)(m0 + arow) * K + kq;
    const float* Bptr = B + (size_t)brow * N + n0 + bcol;
    const size_t Aoff2 = (size_t)64 * K;
    const size_t Boff2 = (size_t)8 * N;

    float acc[8][8];
#pragma unroll
    for (int i = 0; i < 8; i++)
#pragma unroll
        for (int j = 0; j < 8; j++) acc[i][j] = 0.f;

    // prologue: load k-tile 0 straight into smem buffer 0
    {
        float4 a0 = *reinterpret_cast<const float4*>(Aptr);
        float4 a1 = *reinterpret_cast<const float4*>(Aptr + Aoff2);
        float4 b0 = *reinterpret_cast<const float4*>(Bptr);
        float4 b1 = *reinterpret_cast<const float4*>(Bptr + Boff2);
        As[0][kq+0][arow]    = a0.x; As[0][kq+1][arow]    = a0.y;
        As[0][kq+2][arow]    = a0.z; As[0][kq+3][arow]    = a0.w;
        As[0][kq+0][arow+64] = a1.x; As[0][kq+1][arow+64] = a1.y;
        As[0][kq+2][arow+64] = a1.z; As[0][kq+3][arow+64] = a1.w;
        *reinterpret_cast<float4*>(&Bs[0][brow][bcol])   = b0;
        *reinterpret_cast<float4*>(&Bs[0][brow+8][bcol]) = b1;
    }
    __syncthreads();

    int buf = 0;
    for (int kt = 16; kt < K; kt += 16) {
        // prefetch next tile into registers (in flight during compute)
        float4 a0 = *reinterpret_cast<const float4*>(Aptr + kt);
        float4 a1 = *reinterpret_cast<const float4*>(Aptr + Aoff2 + kt);
        float4 b0 = *reinterpret_cast<const float4*>(Bptr + (size_t)kt * N);
        float4 b1 = *reinterpret_cast<const float4*>(Bptr + (size_t)kt * N + Boff2);

        // compute current buffer
#pragma unroll
        for (int k = 0; k < 16; k++) {
            float4 fa0 = *reinterpret_cast<const float4*>(&As[buf][k][ty * 4]);
            float4 fa1 = *reinterpret_cast<const float4*>(&As[buf][k][64 + ty * 4]);
            float4 fb0 = *reinterpret_cast<const float4*>(&Bs[buf][k][tx * 4]);
            float4 fb1 = *reinterpret_cast<const float4*>(&Bs[buf][k][64 + tx * 4]);
            float ra[8] = {fa0.x, fa0.y, fa0.z, fa0.w, fa1.x, fa1.y, fa1.z, fa1.w};
            float rb[8] = {fb0.x, fb0.y, fb0.z, fb0.w, fb1.x, fb1.y, fb1.z, fb1.w};
#pragma unroll
            for (int i = 0; i < 8; i++)
#pragma unroll
                for (int j = 0; j < 8; j++)
                    acc[i][j] = fmaf(ra[i], rb[j], acc[i][j]);
        }

        // commit prefetch into the other buffer
        int nb = buf ^ 1;
        As[nb][kq+0][arow]    = a0.x; As[nb][kq+1][arow]    = a0.y;
        As[nb][kq+2][arow]    = a0.z; As[nb][kq+3][arow]    = a0.w;
        As[nb][kq+0][arow+64] = a1.x; As[nb][kq+1][arow+64] = a1.y;
        As[nb][kq+2][arow+64] = a1.z; As[nb][kq+3][arow+64] = a1.w;
        *reinterpret_cast<float4*>(&Bs[nb][brow][bcol])   = b0;
        *reinterpret_cast<float4*>(&Bs[nb][brow+8][bcol]) = b1;
        __syncthreads();
        buf = nb;
    }

    // last tile
#pragma unroll
    for (int k = 0; k < 16; k++) {
        float4 fa0 = *reinterpret_cast<const float4*>(&As[buf][k][ty * 4]);
        float4 fa1 = *reinterpret_cast<const float4*>(&As[buf][k][64 + ty * 4]);
        float4 fb0 = *reinterpret_cast<const float4*>(&Bs[buf][k][tx * 4]);
        float4 fb1 = *reinterpret_cast<const float4*>(&Bs[buf][k][64 + tx * 4]);
        float ra[8] = {fa0.x, fa0.y, fa0.z, fa0.w, fa1.x, fa1.y, fa1.z, fa1.w};
        float rb[8] = {fb0.x, fb0.y, fb0.z, fb0.w, fb1.x, fb1.y, fb1.z, fb1.w};
#pragma unroll
        for (int i = 0; i < 8; i++)
#pragma unroll
            for (int j = 0; j < 8; j++)
                acc[i][j] = fmaf(ra[i], rb[j], acc[i][j]);
    }

    // epilogue (vectorized float4 stores)
#pragma unroll
    for (int ih = 0; ih < 2; ih++) {
#pragma unroll
        for (int i = 0; i < 4; i++) {
            int row = m0 + ih * 64 + ty * 4 + i;
#pragma unroll
            for (int jh = 0; jh < 2; jh++) {
                int col = n0 + jh * 64 + tx * 4;
                float4 r;
                r.x = acc[ih * 4 + i][jh * 4 + 0];
                r.y = acc[ih * 4 + i][jh * 4 + 1];
                r.z = acc[ih * 4 + i][jh * 4 + 2];
                r.w = acc[ih * 4 + i][jh * 4 + 3];
                float4 bb = *reinterpret_cast<const float4*>(&bias[col]);
                r.x += bb.x; r.y += bb.y; r.z += bb.z; r.w += bb.w;
                if (EPI == 1) {
                    r.x = r.x * normcdff(r.x);
                    r.y = r.y * normcdff(r.y);
                    r.z = r.z * normcdff(r.z);
                    r.w = r.w * normcdff(r.w);
                } else {
                    float4 ad = *reinterpret_cast<const float4*>(
                        &add[(size_t)row * N + col]);
                    r.x += ad.x; r.y += ad.y; r.z += ad.z; r.w += ad.w;
                }
                *reinterpret_cast<float4*>(&C[(size_t)row * N + col]) = r;
            }
        }
    }
}

// ---------------------------------------------------------------------------
extern "C" void kernel_launch(void* const* d_in, const int* in_sizes, int n_in,
                              void* d_out, int out_size)
{
    const float* x     = (const float*)d_in[0];
    const float* Wq    = (const float*)d_in[1];
    const float* Wk    = (const float*)d_in[2];
    const float* Wv    = (const float*)d_in[3];
    const float* Wo    = (const float*)d_in[4];
    const float* bo    = (const float*)d_in[5];
    const float* ln1g  = (const float*)d_in[6];
    const float* ln1b  = (const float*)d_in[7];
    const float* ln2g  = (const float*)d_in[8];
    const float* ln2b  = (const float*)d_in[9];
    const float* W1    = (const float*)d_in[10];
    const float* b1    = (const float*)d_in[11];
    const float* W2    = (const float*)d_in[12];
    const float* b2    = (const float*)d_in[13];
    float* out = (float*)d_out;

    void *p_xn, *p_q, *p_k, *p_v, *p_ctx, *p_attn, *p_an, *p_ff1;
    cudaGetSymbolAddress(&p_xn,   g_xn);
    cudaGetSymbolAddress(&p_q,    g_q);
    cudaGetSymbolAddress(&p_k,    g_k);
    cudaGetSymbolAddress(&p_v,    g_v);
    cudaGetSymbolAddress(&p_ctx,  g_ctx);
    cudaGetSymbolAddress(&p_attn, g_attn);
    cudaGetSymbolAddress(&p_an,   g_an);
    cudaGetSymbolAddress(&p_ff1,  g_ff1);
    float* xn   = (float*)p_xn;
    float* q    = (float*)p_q;
    float* k    = (float*)p_k;
    float* v    = (float*)p_v;
    float* ctx  = (float*)p_ctx;
    float* attn = (float*)p_attn;
    float* an   = (float*)p_an;
    float* ff1  = (float*)p_ff1;

    cudaFuncSetAttribute(qkv_kernel,  cudaFuncAttributeMaxDynamicSharedMemorySize, (int)QKV_SMEM);
    cudaFuncSetAttribute(attn_kernel, cudaFuncAttributeMaxDynamicSharedMemorySize, (int)ATT_SMEM);

    // 1. pre-LN
    ln_kernel<<<NROWS, 256>>>(x, ln1g, ln1b, xn);
    // 2. per-head QKV projections (head-major output)
    qkv_kernel<<<2048, 256, QKV_SMEM>>>(xn, Wq, Wk, Wv, q, k, v);
    // 3. flash attention -> ctx [n,s,E]
    attn_kernel<<<dim3(SEQ / 64, NBATCH * NH), 256, ATT_SMEM>>>(q, k, v, ctx);
    // 4. output projection + residual 1
    sgemm_kernel<0><<<dim3(EMB / 128, NROWS / 128), 256>>>(ctx, Wo, bo, x, attn,
                                                           NROWS, EMB, EMB);
    // 5. LN2
    ln_kernel<<<NROWS, 256>>>(attn, ln2g, ln2b, an);
    // 6. FFN up + exact GELU
    sgemm_kernel<1><<<dim3(FFND / 128, NROWS / 128), 256>>>(an, W1, b1, nullptr, ff1,
                                                            NROWS, FFND, EMB);
    // 7. FFN down + bias + residual 2 -> out
    sgemm_kernel<2><<<dim3(EMB / 128, NROWS / 128), 256>>>(ff1, W2, b2, attn, out,
                                                           NROWS, EMB, FFND);
}